// round 6
// baseline (speedup 1.0000x reference)
#include <cuda_runtime.h>
#include <cuda_bf16.h>
#include <cstdint>
#include <math.h>

// Problem constants
#define Bb 8
#define Tt 2048
#define Cc 2048
#define HSs 64
#define Hh (Cc / HSs)          // 32
#define Mtot (Bb * Tt)         // 16384
#define MK ((size_t)Mtot * Cc)
#define NK ((size_t)Cc * Cc)
#define DIVI 0.125f

// ---------------------------------------------------------------------------
// Scratch (device globals)
// ---------------------------------------------------------------------------
__device__ __nv_bfloat16 g_ah[4 * MK];   // token-shift-mixed A, hi   (r,k,v,g)
__device__ __nv_bfloat16 g_al[4 * MK];   // token-shift-mixed A, lo
__device__ __nv_bfloat16 g_wh[5 * NK];   // W^T (N-major, K-contig), hi
__device__ __nv_bfloat16 g_wl[5 * NK];   // W^T lo
__device__ __nv_bfloat16 g_fah[MK];      // final A (yn*silu-gated), hi
__device__ __nv_bfloat16 g_fal[MK];      // final A lo
__device__ float g_r[MK];
__device__ float g_k[MK];
__device__ float g_v[MK];
__device__ float g_g[MK];
__device__ float g_y[MK];

// ---------------------------------------------------------------------------
// helpers
// ---------------------------------------------------------------------------
__device__ __forceinline__ uint32_t smem_to_u32(const void* p) {
    uint32_t a;
    asm("{ .reg .u64 t; cvta.to.shared.u64 t, %1; cvt.u32.u64 %0, t; }" : "=r"(a) : "l"(p));
    return a;
}
__device__ __forceinline__ void split1(float v, __nv_bfloat16& h, __nv_bfloat16& l) {
    h = __float2bfloat16(v);
    l = __float2bfloat16(v - __bfloat162float(h));
}

#define LDSM_X4(r, a)                                                          \
    asm volatile("ldmatrix.sync.aligned.m8n8.x4.shared.b16 {%0,%1,%2,%3},[%4];"\
                 : "=r"((r)[0]), "=r"((r)[1]), "=r"((r)[2]), "=r"((r)[3])      \
                 : "r"(a))

#define MMA16816(c, a, b0, b1)                                                 \
    asm volatile("mma.sync.aligned.m16n8k16.row.col.f32.bf16.bf16.f32 "        \
                 "{%0,%1,%2,%3},{%4,%5,%6,%7},{%8,%9},{%0,%1,%2,%3};"          \
                 : "+f"((c)[0]), "+f"((c)[1]), "+f"((c)[2]), "+f"((c)[3])      \
                 : "r"((a)[0]), "r"((a)[1]), "r"((a)[2]), "r"((a)[3]),         \
                   "r"(b0), "r"(b1))

#define CP_ASYNC16(dst, src)                                                   \
    asm volatile("cp.async.cg.shared.global [%0],[%1],16;"                     \
                 :: "r"(dst), "l"(src) : "memory")
#define CP_COMMIT() asm volatile("cp.async.commit_group;" ::: "memory")
#define CP_WAIT(n)  asm volatile("cp.async.wait_group %0;" :: "n"(n) : "memory")

// smem geometry: pitch 80B (64B data + 16B pad), conflict-free ldmatrix
#define PITCHB 80
#define A_MATB (256 * PITCHB)          // 20480 B  (Ah or Al)
#define B_MATB (128 * PITCHB)          // 10240 B  (Bh or Bl)
#define B_OFS  (2 * A_MATB)            // 40960
#define STAGEB (2 * A_MATB + 2 * B_MATB)  // 61440 B per stage
#define GEMM_SMEM (3 * STAGEB)         // 184320 B

// ---------------------------------------------------------------------------
// Convert x -> 4 mixed A matrices (bf16 hi/lo), token shift fused
// ---------------------------------------------------------------------------
__global__ __launch_bounds__(256)
void conv_x(const float* __restrict__ x,
            const float* __restrict__ tmr, const float* __restrict__ tmk,
            const float* __restrict__ tmv, const float* __restrict__ tmg)
{
    const size_t idx = (size_t)blockIdx.x * blockDim.x + threadIdx.x; // M*C/4
    const int m = (int)(idx >> 9);
    const int c4 = ((int)idx & 511) * 4;
    const int tpos = m & (Tt - 1);

    const float4 xv = *(const float4*)(x + (size_t)m * Cc + c4);
    float4 xp = make_float4(0.f, 0.f, 0.f, 0.f);
    if (tpos) xp = *(const float4*)(x + (size_t)(m - 1) * Cc + c4);

    const float* tms[4] = {tmr, tmk, tmv, tmg};
    const size_t ofs = (size_t)m * Cc + c4;
#pragma unroll
    for (int a = 0; a < 4; a++) {
        float4 tm = *(const float4*)(tms[a] + c4);
        float4 v;
        v.x = xp.x + tm.x * (xv.x - xp.x);
        v.y = xp.y + tm.y * (xv.y - xp.y);
        v.z = xp.z + tm.z * (xv.z - xp.z);
        v.w = xp.w + tm.w * (xv.w - xp.w);
        __nv_bfloat16 h0, h1, h2, h3, l0, l1, l2, l3;
        split1(v.x, h0, l0); split1(v.y, h1, l1);
        split1(v.z, h2, l2); split1(v.w, h3, l3);
        __nv_bfloat162* dh = (__nv_bfloat162*)(g_ah + a * MK + ofs);
        __nv_bfloat162* dl = (__nv_bfloat162*)(g_al + a * MK + ofs);
        dh[0] = __nv_bfloat162(h0, h1); dh[1] = __nv_bfloat162(h2, h3);
        dl[0] = __nv_bfloat162(l0, l1); dl[1] = __nv_bfloat162(l2, l3);
    }
}

// ---------------------------------------------------------------------------
// Transpose + split weights: Wt[n][k] = W[k][n]
// ---------------------------------------------------------------------------
__global__ __launch_bounds__(256)
void conv_w(const float* __restrict__ W0, const float* __restrict__ W1,
            const float* __restrict__ W2, const float* __restrict__ W3,
            const float* __restrict__ W4)
{
    const float* Ws[5] = {W0, W1, W2, W3, W4};
    const float* W = Ws[blockIdx.z];
    __nv_bfloat16* oh = g_wh + (size_t)blockIdx.z * NK;
    __nv_bfloat16* ol = g_wl + (size_t)blockIdx.z * NK;

    __shared__ float tile[32][33];
    const int n0 = blockIdx.x * 32, k0 = blockIdx.y * 32;
    const int tx = threadIdx.x & 31, ty = threadIdx.x >> 5;
#pragma unroll
    for (int j = 0; j < 4; j++)
        tile[ty + j * 8][tx] = W[(size_t)(k0 + ty + j * 8) * Cc + n0 + tx];
    __syncthreads();
#pragma unroll
    for (int j = 0; j < 4; j++) {
        float v = tile[tx][ty + j * 8];
        __nv_bfloat16 h, l;
        split1(v, h, l);
        const size_t o = (size_t)(n0 + ty + j * 8) * Cc + k0 + tx;
        oh[o] = h; ol[o] = l;
    }
}

// ---------------------------------------------------------------------------
// HMMA GEMM: out[M,N] = (Ah+Al)[M,K] @ (Bh+Bl)[N,K]^T   (3-term bf16)
// 256x128 CTA tile, 8 warps of 64x64, K-chunk 32, 3-stage cp.async,
// single __syncthreads per chunk, B-fragments streamed.
// ---------------------------------------------------------------------------
template <int SILU>
__global__ __launch_bounds__(256, 1)
void mm_hmma(const __nv_bfloat16* __restrict__ Ah, const __nv_bfloat16* __restrict__ Al,
             const __nv_bfloat16* __restrict__ Bh, const __nv_bfloat16* __restrict__ Bl,
             float* __restrict__ out)
{
    extern __shared__ __align__(128) char smem[];
    const uint32_t sb = smem_to_u32(smem);
    const int tid = threadIdx.x;
    const int wid = tid >> 5, lane = tid & 31;
    const int m0 = blockIdx.y * 256, n0 = blockIdx.x * 128;
    const int wm = (wid >> 1) * 64;    // 0,64,128,192
    const int wn = (wid & 1) * 64;     // 0,64

    const __nv_bfloat16* a_h = Ah + (size_t)m0 * Cc;
    const __nv_bfloat16* a_l = Al + (size_t)m0 * Cc;
    const __nv_bfloat16* b_h = Bh + (size_t)n0 * Cc;
    const __nv_bfloat16* b_l = Bl + (size_t)n0 * Cc;

    // cp.async maps (256 threads):
    //  A: row = tid (0..255), 4x16B hi + 4x16B lo
    //  B: row = tid>>1 (0..127), 2x16B hi + 2x16B lo at col (tid&1)*2
    const int rA = tid;
    const int rB = tid >> 1, cB = (tid & 1) * 2;

    float acc[4][8][4];
#pragma unroll
    for (int i = 0; i < 4; i++)
#pragma unroll
        for (int j = 0; j < 8; j++)
#pragma unroll
            for (int q = 0; q < 4; q++) acc[i][j][q] = 0.f;

    const uint32_t arow = (uint32_t)(wm + (lane & 15));
    const uint32_t brow = (uint32_t)(wn + (lane & 15));
    const uint32_t kofs = (uint32_t)((lane >> 4) * 16);

    const int NC = Cc / 32;   // 64

    auto load_chunk = [&](uint32_t st, int kb) {
        const uint32_t dA = st + rA * PITCHB;
        const __nv_bfloat16* sAh = a_h + (size_t)rA * Cc + kb;
        const __nv_bfloat16* sAl = a_l + (size_t)rA * Cc + kb;
#pragma unroll
        for (int c = 0; c < 4; c++) {
            CP_ASYNC16(dA + c * 16, sAh + c * 8);
            CP_ASYNC16(dA + A_MATB + c * 16, sAl + c * 8);
        }
        const uint32_t dB = st + B_OFS + rB * PITCHB + cB * 16;
        const __nv_bfloat16* sBh = b_h + (size_t)rB * Cc + kb + cB * 8;
        const __nv_bfloat16* sBl = b_l + (size_t)rB * Cc + kb + cB * 8;
        CP_ASYNC16(dB, sBh);           CP_ASYNC16(dB + 16, sBh + 8);
        CP_ASYNC16(dB + B_MATB, sBl);  CP_ASYNC16(dB + B_MATB + 16, sBl + 8);
    };

    // prologue: chunks 0,1 -> stages 0,1
    load_chunk(sb, 0);           CP_COMMIT();
    load_chunk(sb + STAGEB, 32); CP_COMMIT();

    int s_cur = 0, s_nxt = 2;
    for (int c = 0; c < NC; c++) {
        if (c < NC - 1) { CP_WAIT(1); } else { CP_WAIT(0); }
        __syncthreads();

        if (c + 2 < NC) {
            load_chunk(sb + s_nxt * STAGEB, (c + 2) * 32);
            CP_COMMIT();
        }

        const uint32_t st = sb + s_cur * STAGEB;
#pragma unroll
        for (int kh = 0; kh < 2; kh++) {
            const uint32_t kb2 = kh * 32 + kofs;
            uint32_t ahf[4][4], alf[4][4];
#pragma unroll
            for (int mf = 0; mf < 4; mf++) {
                uint32_t addr = st + (arow + mf * 16) * PITCHB + kb2;
                LDSM_X4(ahf[mf], addr);
                LDSM_X4(alf[mf], addr + A_MATB);
            }
#pragma unroll
            for (int nb = 0; nb < 4; nb++) {
                uint32_t bhf[4], blf[4];
                uint32_t addr = st + B_OFS + (brow + nb * 16) * PITCHB + kb2;
                LDSM_X4(bhf, addr);
                LDSM_X4(blf, addr + B_MATB);
#pragma unroll
                for (int mf = 0; mf < 4; mf++) {
                    MMA16816(acc[mf][nb * 2 + 0], ahf[mf], bhf[0], bhf[2]);
                    MMA16816(acc[mf][nb * 2 + 1], ahf[mf], bhf[1], bhf[3]);
                }
#pragma unroll
                for (int mf = 0; mf < 4; mf++) {
                    MMA16816(acc[mf][nb * 2 + 0], alf[mf], bhf[0], bhf[2]);
                    MMA16816(acc[mf][nb * 2 + 1], alf[mf], bhf[1], bhf[3]);
                }
#pragma unroll
                for (int mf = 0; mf < 4; mf++) {
                    MMA16816(acc[mf][nb * 2 + 0], ahf[mf], blf[0], blf[2]);
                    MMA16816(acc[mf][nb * 2 + 1], ahf[mf], blf[1], blf[3]);
                }
            }
        }
        s_cur++; if (s_cur == 3) s_cur = 0;
        s_nxt++; if (s_nxt == 3) s_nxt = 0;
    }

    // epilogue
    const int g = lane >> 2, tg = lane & 3;
#pragma unroll
    for (int mf = 0; mf < 4; mf++) {
#pragma unroll
        for (int nf = 0; nf < 8; nf++) {
            const int row = m0 + wm + mf * 16 + g;
            const int col = n0 + wn + nf * 8 + tg * 2;
            float2 v0 = make_float2(acc[mf][nf][0], acc[mf][nf][1]);
            float2 v1 = make_float2(acc[mf][nf][2], acc[mf][nf][3]);
            if (SILU) {
                v0.x = v0.x / (1.f + expf(-v0.x));
                v0.y = v0.y / (1.f + expf(-v0.y));
                v1.x = v1.x / (1.f + expf(-v1.x));
                v1.y = v1.y / (1.f + expf(-v1.y));
            }
            *(float2*)(out + (size_t)row * Cc + col) = v0;
            *(float2*)(out + (size_t)(row + 8) * Cc + col) = v1;
        }
    }
}

// ---------------------------------------------------------------------------
// WKV5 recurrence: 128 threads per (b,h), split state rows in halves.
// ---------------------------------------------------------------------------
__global__ __launch_bounds__(128)
void wkv5_k(const float* __restrict__ decay, const float* __restrict__ faaaa)
{
    const int bh = blockIdx.x;
    const int h = bh & (Hh - 1);
    const int b = bh >> 5;
    const int tid = threadIdx.x;
    const int j = tid & 63;
    const int half = tid >> 6;
    const int i0 = half * 32;

    float u[32], w[32], S[32];
#pragma unroll
    for (int q = 0; q < 32; q++) {
        u[q] = faaaa[h * HSs + i0 + q];
        w[q] = expf(-expf(decay[h * HSs + i0 + q]));
        S[q] = 0.f;
    }

    __shared__ float2 rk[2][HSs];
    __shared__ float part[2][2][HSs];

    const size_t base = (size_t)b * Tt * Cc + (size_t)h * HSs + j;
    const float* rp = g_r + base;
    const float* kp = g_k + base;
    const float* vp = g_v + base;
    float* yp = g_y + base;

    float rc = rp[0], kc = kp[0], vc = vp[0];

    for (int t = 0; t < Tt; t++) {
        const int p = t & 1;
        if (!half) rk[p][j] = make_float2(rc, kc);
        const float vj = vc;
        __syncthreads();

        if (t + 1 < Tt) {
            const size_t ofs = (size_t)(t + 1) * Cc;
            rc = rp[ofs]; kc = kp[ofs]; vc = vp[ofs];
        }

        float y = 0.f;
#pragma unroll
        for (int q = 0; q < 32; q++) {
            const float2 x = rk[p][i0 + q];
            const float kv = x.y * vj;
            y = fmaf(x.x, fmaf(u[q], kv, S[q]), y);
            S[q] = fmaf(w[q], S[q], kv);
        }
        part[p][half][j] = y;
        __syncthreads();

        if (!half) yp[(size_t)t * Cc] = part[p][0][j] + part[p][1][j];
    }
}

// ---------------------------------------------------------------------------
// GroupNorm(y/8)*ln_w+ln_b, multiply silu-gate, split bf16 hi/lo
// ---------------------------------------------------------------------------
__global__ __launch_bounds__(256)
void gnorm_k(const float* __restrict__ lnw, const float* __restrict__ lnb)
{
    const int gidx = blockIdx.x * 8 + (threadIdx.x >> 5);
    const int lane = threadIdx.x & 31;
    const int h = gidx & (Hh - 1);
    const size_t base = (size_t)gidx * HSs;

    float y0 = g_y[base + lane] * DIVI;
    float y1 = g_y[base + 32 + lane] * DIVI;

    float s = y0 + y1;
#pragma unroll
    for (int o = 16; o; o >>= 1) s += __shfl_xor_sync(0xFFFFFFFFu, s, o);
    const float mean = s * (1.f / 64.f);

    const float d0 = y0 - mean, d1 = y1 - mean;
    float v = d0 * d0 + d1 * d1;
#pragma unroll
    for (int o = 16; o; o >>= 1) v += __shfl_xor_sync(0xFFFFFFFFu, v, o);
    const float rstd = rsqrtf(v * (1.f / 64.f) + 1e-5f);

    const int li = h * HSs + lane;
    const float p0 = (d0 * rstd * lnw[li] + lnb[li]) * g_g[base + lane];
    const float p1 = (d1 * rstd * lnw[li + 32] + lnb[li + 32]) * g_g[base + 32 + lane];

    __nv_bfloat16 h0, l0, h1, l1;
    split1(p0, h0, l0); split1(p1, h1, l1);
    g_fah[base + lane] = h0;      g_fal[base + lane] = l0;
    g_fah[base + 32 + lane] = h1; g_fal[base + 32 + lane] = l1;
}

// ---------------------------------------------------------------------------
// launch
// ---------------------------------------------------------------------------
extern "C" void kernel_launch(void* const* d_in, const int* in_sizes, int n_in,
                              void* d_out, int out_size)
{
    const float* x     = (const float*)d_in[0];
    const float* tmk   = (const float*)d_in[1];
    const float* tmv   = (const float*)d_in[2];
    const float* tmr   = (const float*)d_in[3];
    const float* tmg   = (const float*)d_in[4];
    const float* decay = (const float*)d_in[5];
    const float* faaaa = (const float*)d_in[6];
    const float* Wr    = (const float*)d_in[7];
    const float* Wk    = (const float*)d_in[8];
    const float* Wv    = (const float*)d_in[9];
    const float* Wg    = (const float*)d_in[10];
    const float* Wo    = (const float*)d_in[11];
    const float* lnw   = (const float*)d_in[12];
    const float* lnb   = (const float*)d_in[13];
    float* out = (float*)d_out;

    cudaFuncSetAttribute(mm_hmma<0>, cudaFuncAttributeMaxDynamicSharedMemorySize, GEMM_SMEM);
    cudaFuncSetAttribute(mm_hmma<1>, cudaFuncAttributeMaxDynamicSharedMemorySize, GEMM_SMEM);

    void *pah, *pal, *pwh, *pwl, *pfah, *pfal, *pr, *pk, *pv, *pg;
    cudaGetSymbolAddress(&pah, g_ah);
    cudaGetSymbolAddress(&pal, g_al);
    cudaGetSymbolAddress(&pwh, g_wh);
    cudaGetSymbolAddress(&pwl, g_wl);
    cudaGetSymbolAddress(&pfah, g_fah);
    cudaGetSymbolAddress(&pfal, g_fal);
    cudaGetSymbolAddress(&pr, g_r);
    cudaGetSymbolAddress(&pk, g_k);
    cudaGetSymbolAddress(&pv, g_v);
    cudaGetSymbolAddress(&pg, g_g);
    const __nv_bfloat16* ah = (const __nv_bfloat16*)pah;
    const __nv_bfloat16* al = (const __nv_bfloat16*)pal;
    const __nv_bfloat16* wh = (const __nv_bfloat16*)pwh;
    const __nv_bfloat16* wl = (const __nv_bfloat16*)pwl;

    conv_x<<<(unsigned)(MK / 4 / 256), 256>>>(x, tmr, tmk, tmv, tmg);
    conv_w<<<dim3(Cc / 32, Cc / 32, 5), 256>>>(Wr, Wk, Wv, Wg, Wo);

    dim3 grid(Cc / 128, Mtot / 256);   // (16, 64)

    mm_hmma<0><<<grid, 256, GEMM_SMEM>>>(ah + 0 * MK, al + 0 * MK, wh + 0 * NK, wl + 0 * NK, (float*)pr);
    mm_hmma<0><<<grid, 256, GEMM_SMEM>>>(ah + 1 * MK, al + 1 * MK, wh + 1 * NK, wl + 1 * NK, (float*)pk);
    mm_hmma<0><<<grid, 256, GEMM_SMEM>>>(ah + 2 * MK, al + 2 * MK, wh + 2 * NK, wl + 2 * NK, (float*)pv);
    mm_hmma<1><<<grid, 256, GEMM_SMEM>>>(ah + 3 * MK, al + 3 * MK, wh + 3 * NK, wl + 3 * NK, (float*)pg);

    wkv5_k<<<Bb * Hh, 128>>>(decay, faaaa);

    gnorm_k<<<(Bb * Tt * Hh) / 8, 256>>>(lnw, lnb);

    mm_hmma<0><<<grid, 256, GEMM_SMEM>>>((const __nv_bfloat16*)pfah, (const __nv_bfloat16*)pfal,
                                         wh + 4 * NK, wl + 4 * NK, out);
}

// round 11
// speedup vs baseline: 1.1783x; 1.1783x over previous
#include <cuda_runtime.h>
#include <cuda_bf16.h>
#include <cstdint>
#include <math.h>

// Problem constants
#define Bb 8
#define Tt 2048
#define Cc 2048
#define HSs 64
#define Hh (Cc / HSs)          // 32
#define Mtot (Bb * Tt)         // 16384
#define MK ((size_t)Mtot * Cc)
#define NK ((size_t)Cc * Cc)
#define DIVI 0.125f

// ---------------------------------------------------------------------------
// Scratch (device globals)
// ---------------------------------------------------------------------------
__device__ __nv_bfloat16 g_ah[4 * MK];   // token-shift-mixed A, hi   (r,k,v,g)
__device__ __nv_bfloat16 g_al[4 * MK];   // token-shift-mixed A, lo
__device__ __nv_bfloat16 g_wh[5 * NK];   // W^T (N-major, K-contig), hi
__device__ __nv_bfloat16 g_wl[5 * NK];   // W^T lo
__device__ __nv_bfloat16 g_fah[MK];      // final A (yn*silu-gated), hi
__device__ __nv_bfloat16 g_fal[MK];      // final A lo
__device__ float g_r[MK];
__device__ float g_k[MK];
__device__ float g_v[MK];
__device__ float g_g[MK];
__device__ float g_y[MK];

// ---------------------------------------------------------------------------
// helpers
// ---------------------------------------------------------------------------
__device__ __forceinline__ uint32_t smem_to_u32(const void* p) {
    uint32_t a;
    asm("{ .reg .u64 t; cvta.to.shared.u64 t, %1; cvt.u32.u64 %0, t; }" : "=r"(a) : "l"(p));
    return a;
}
__device__ __forceinline__ void split1(float v, __nv_bfloat16& h, __nv_bfloat16& l) {
    h = __float2bfloat16(v);
    l = __float2bfloat16(v - __bfloat162float(h));
}

#define LDSM_X4(r, a)                                                          \
    asm volatile("ldmatrix.sync.aligned.m8n8.x4.shared.b16 {%0,%1,%2,%3},[%4];"\
                 : "=r"((r)[0]), "=r"((r)[1]), "=r"((r)[2]), "=r"((r)[3])      \
                 : "r"(a))

#define MMA16816(c, a, b0, b1)                                                 \
    asm volatile("mma.sync.aligned.m16n8k16.row.col.f32.bf16.bf16.f32 "        \
                 "{%0,%1,%2,%3},{%4,%5,%6,%7},{%8,%9},{%0,%1,%2,%3};"          \
                 : "+f"((c)[0]), "+f"((c)[1]), "+f"((c)[2]), "+f"((c)[3])      \
                 : "r"((a)[0]), "r"((a)[1]), "r"((a)[2]), "r"((a)[3]),         \
                   "r"(b0), "r"(b1))

#define CP_ASYNC16(dst, src)                                                   \
    asm volatile("cp.async.cg.shared.global [%0],[%1],16;"                     \
                 :: "r"(dst), "l"(src) : "memory")
#define CP_COMMIT() asm volatile("cp.async.commit_group;" ::: "memory")
#define CP_WAIT(n)  asm volatile("cp.async.wait_group %0;" :: "n"(n) : "memory")

// smem: 64B pitch + XOR swizzle (granule ^= (row>>1)&3).
// Per 8-row ldmatrix phase this covers all 32 banks -> conflict-free.
#define SWZ_ADDR(base, row, g) \
    ((base) + (uint32_t)(row) * 64u + ((((uint32_t)(g)) ^ (((uint32_t)(row) >> 1) & 3u)) << 4))

#define MAT_B  8192                     // 128 rows x 64 B
#define STAGEB (4 * MAT_B)              // 32768 (Ah, Al, Bh, Bl)
#define GEMM_SMEM (3 * STAGEB)          // 98304 per CTA; 2 CTAs/SM = 192 KB

// ---------------------------------------------------------------------------
// Convert x -> 4 mixed A matrices (bf16 hi/lo), token shift fused
// ---------------------------------------------------------------------------
__global__ __launch_bounds__(256)
void conv_x(const float* __restrict__ x,
            const float* __restrict__ tmr, const float* __restrict__ tmk,
            const float* __restrict__ tmv, const float* __restrict__ tmg)
{
    const size_t idx = (size_t)blockIdx.x * blockDim.x + threadIdx.x; // M*C/4
    const int m = (int)(idx >> 9);
    const int c4 = ((int)idx & 511) * 4;
    const int tpos = m & (Tt - 1);

    const float4 xv = *(const float4*)(x + (size_t)m * Cc + c4);
    float4 xp = make_float4(0.f, 0.f, 0.f, 0.f);
    if (tpos) xp = *(const float4*)(x + (size_t)(m - 1) * Cc + c4);

    const float* tms[4] = {tmr, tmk, tmv, tmg};
    const size_t ofs = (size_t)m * Cc + c4;
#pragma unroll
    for (int a = 0; a < 4; a++) {
        float4 tm = *(const float4*)(tms[a] + c4);
        float4 v;
        v.x = xp.x + tm.x * (xv.x - xp.x);
        v.y = xp.y + tm.y * (xv.y - xp.y);
        v.z = xp.z + tm.z * (xv.z - xp.z);
        v.w = xp.w + tm.w * (xv.w - xp.w);
        __nv_bfloat16 h0, h1, h2, h3, l0, l1, l2, l3;
        split1(v.x, h0, l0); split1(v.y, h1, l1);
        split1(v.z, h2, l2); split1(v.w, h3, l3);
        __nv_bfloat162* dh = (__nv_bfloat162*)(g_ah + a * MK + ofs);
        __nv_bfloat162* dl = (__nv_bfloat162*)(g_al + a * MK + ofs);
        dh[0] = __nv_bfloat162(h0, h1); dh[1] = __nv_bfloat162(h2, h3);
        dl[0] = __nv_bfloat162(l0, l1); dl[1] = __nv_bfloat162(l2, l3);
    }
}

// ---------------------------------------------------------------------------
// Transpose + split weights: Wt[n][k] = W[k][n]
// ---------------------------------------------------------------------------
__global__ __launch_bounds__(256)
void conv_w(const float* __restrict__ W0, const float* __restrict__ W1,
            const float* __restrict__ W2, const float* __restrict__ W3,
            const float* __restrict__ W4)
{
    const float* Ws[5] = {W0, W1, W2, W3, W4};
    const float* W = Ws[blockIdx.z];
    __nv_bfloat16* oh = g_wh + (size_t)blockIdx.z * NK;
    __nv_bfloat16* ol = g_wl + (size_t)blockIdx.z * NK;

    __shared__ float tile[32][33];
    const int n0 = blockIdx.x * 32, k0 = blockIdx.y * 32;
    const int tx = threadIdx.x & 31, ty = threadIdx.x >> 5;
#pragma unroll
    for (int j = 0; j < 4; j++)
        tile[ty + j * 8][tx] = W[(size_t)(k0 + ty + j * 8) * Cc + n0 + tx];
    __syncthreads();
#pragma unroll
    for (int j = 0; j < 4; j++) {
        float v = tile[tx][ty + j * 8];
        __nv_bfloat16 h, l;
        split1(v, h, l);
        const size_t o = (size_t)(n0 + ty + j * 8) * Cc + k0 + tx;
        oh[o] = h; ol[o] = l;
    }
}

// ---------------------------------------------------------------------------
// HMMA GEMM: out[M,N] = (Ah+Al)[M,K] @ (Bh+Bl)[N,K]^T   (3-term bf16)
// 128x128 CTA tile, 8 warps of 64x32, K-chunk 32, 3-stage cp.async,
// single __syncthreads per chunk, 2 CTAs/SM (independent barrier domains).
// ---------------------------------------------------------------------------
template <int SILU>
__global__ __launch_bounds__(256, 2)
void mm_hmma(const __nv_bfloat16* __restrict__ Ah, const __nv_bfloat16* __restrict__ Al,
             const __nv_bfloat16* __restrict__ Bh, const __nv_bfloat16* __restrict__ Bl,
             float* __restrict__ out)
{
    extern __shared__ __align__(128) char smem[];
    const uint32_t sb = smem_to_u32(smem);
    const int tid = threadIdx.x;
    const int wid = tid >> 5, lane = tid & 31;
    const int m0 = blockIdx.y * 128, n0 = blockIdx.x * 128;
    const int wm = (wid >> 2) * 64;    // 0,64
    const int wn = (wid & 3) * 32;     // 0,32,64,96

    const __nv_bfloat16* a_h = Ah + (size_t)m0 * Cc;
    const __nv_bfloat16* a_l = Al + (size_t)m0 * Cc;
    const __nv_bfloat16* b_h = Bh + (size_t)n0 * Cc;
    const __nv_bfloat16* b_l = Bl + (size_t)n0 * Cc;

    // cp.async map (256 threads): row = tid>>1 (0..127), granules g, g+1
    const int rL = tid >> 1;
    const int gL = (tid & 1) * 2;

    float acc[4][4][4];
#pragma unroll
    for (int i = 0; i < 4; i++)
#pragma unroll
        for (int j = 0; j < 4; j++)
#pragma unroll
            for (int q = 0; q < 4; q++) acc[i][j][q] = 0.f;

    const int arow = wm + (lane & 15);
    const int brow = wn + (lane & 15);
    const int gfr = lane >> 4;           // granule half for ldmatrix (0/1)

    const int NC = Cc / 32;   // 64

    auto load_chunk = [&](uint32_t st, int kb) {
        const __nv_bfloat16* sAh = a_h + (size_t)rL * Cc + kb + gL * 8;
        const __nv_bfloat16* sAl = a_l + (size_t)rL * Cc + kb + gL * 8;
        const __nv_bfloat16* sBh = b_h + (size_t)rL * Cc + kb + gL * 8;
        const __nv_bfloat16* sBl = b_l + (size_t)rL * Cc + kb + gL * 8;
        const uint32_t d0 = SWZ_ADDR(st, rL, gL);
        const uint32_t d1 = SWZ_ADDR(st, rL, gL + 1);
        CP_ASYNC16(d0, sAh);                 CP_ASYNC16(d1, sAh + 8);
        CP_ASYNC16(d0 + MAT_B, sAl);         CP_ASYNC16(d1 + MAT_B, sAl + 8);
        CP_ASYNC16(d0 + 2 * MAT_B, sBh);     CP_ASYNC16(d1 + 2 * MAT_B, sBh + 8);
        CP_ASYNC16(d0 + 3 * MAT_B, sBl);     CP_ASYNC16(d1 + 3 * MAT_B, sBl + 8);
    };

    // prologue: chunks 0,1 -> stages 0,1
    load_chunk(sb, 0);           CP_COMMIT();
    load_chunk(sb + STAGEB, 32); CP_COMMIT();

    int s_cur = 0, s_nxt = 2;
    for (int c = 0; c < NC; c++) {
        if (c < NC - 1) { CP_WAIT(1); } else { CP_WAIT(0); }
        __syncthreads();

        if (c + 2 < NC) {
            load_chunk(sb + s_nxt * STAGEB, (c + 2) * 32);
            CP_COMMIT();
        }

        const uint32_t st = sb + s_cur * STAGEB;
#pragma unroll
        for (int kh = 0; kh < 2; kh++) {
            const int g = kh * 2 + gfr;   // granule index 0..3
            uint32_t ahf[4][4], alf[4][4], bhf[2][4], blf[2][4];
#pragma unroll
            for (int mf = 0; mf < 4; mf++) {
                const int row = arow + mf * 16;
                LDSM_X4(ahf[mf], SWZ_ADDR(st, row, g));
                LDSM_X4(alf[mf], SWZ_ADDR(st + MAT_B, row, g));
            }
#pragma unroll
            for (int nb = 0; nb < 2; nb++) {
                const int row = brow + nb * 16;
                LDSM_X4(bhf[nb], SWZ_ADDR(st + 2 * MAT_B, row, g));
                LDSM_X4(blf[nb], SWZ_ADDR(st + 3 * MAT_B, row, g));
            }
            // term-major: independent accumulator chains
#pragma unroll
            for (int mf = 0; mf < 4; mf++)
#pragma unroll
                for (int nf = 0; nf < 4; nf++) {
                    const int nb = nf >> 1, o = nf & 1;
                    MMA16816(acc[mf][nf], ahf[mf], bhf[nb][o], bhf[nb][o + 2]);
                }
#pragma unroll
            for (int mf = 0; mf < 4; mf++)
#pragma unroll
                for (int nf = 0; nf < 4; nf++) {
                    const int nb = nf >> 1, o = nf & 1;
                    MMA16816(acc[mf][nf], alf[mf], bhf[nb][o], bhf[nb][o + 2]);
                }
#pragma unroll
            for (int mf = 0; mf < 4; mf++)
#pragma unroll
                for (int nf = 0; nf < 4; nf++) {
                    const int nb = nf >> 1, o = nf & 1;
                    MMA16816(acc[mf][nf], ahf[mf], blf[nb][o], blf[nb][o + 2]);
                }
        }
        s_cur++; if (s_cur == 3) s_cur = 0;
        s_nxt++; if (s_nxt == 3) s_nxt = 0;
    }

    // epilogue
    const int g2 = lane >> 2, tg = lane & 3;
#pragma unroll
    for (int mf = 0; mf < 4; mf++) {
#pragma unroll
        for (int nf = 0; nf < 4; nf++) {
            const int row = m0 + wm + mf * 16 + g2;
            const int col = n0 + wn + nf * 8 + tg * 2;
            float2 v0 = make_float2(acc[mf][nf][0], acc[mf][nf][1]);
            float2 v1 = make_float2(acc[mf][nf][2], acc[mf][nf][3]);
            if (SILU) {
                v0.x = v0.x / (1.f + expf(-v0.x));
                v0.y = v0.y / (1.f + expf(-v0.y));
                v1.x = v1.x / (1.f + expf(-v1.x));
                v1.y = v1.y / (1.f + expf(-v1.y));
            }
            *(float2*)(out + (size_t)row * Cc + col) = v0;
            *(float2*)(out + (size_t)(row + 8) * Cc + col) = v1;
        }
    }
}

// ---------------------------------------------------------------------------
// WKV5 recurrence: 128 threads per (b,h), split state rows in halves.
// ---------------------------------------------------------------------------
__global__ __launch_bounds__(128)
void wkv5_k(const float* __restrict__ decay, const float* __restrict__ faaaa)
{
    const int bh = blockIdx.x;
    const int h = bh & (Hh - 1);
    const int b = bh >> 5;
    const int tid = threadIdx.x;
    const int j = tid & 63;
    const int half = tid >> 6;
    const int i0 = half * 32;

    float u[32], w[32], S[32];
#pragma unroll
    for (int q = 0; q < 32; q++) {
        u[q] = faaaa[h * HSs + i0 + q];
        w[q] = expf(-expf(decay[h * HSs + i0 + q]));
        S[q] = 0.f;
    }

    __shared__ float2 rk[2][HSs];
    __shared__ float part[2][2][HSs];

    const size_t base = (size_t)b * Tt * Cc + (size_t)h * HSs + j;
    const float* rp = g_r + base;
    const float* kp = g_k + base;
    const float* vp = g_v + base;
    float* yp = g_y + base;

    float rc = rp[0], kc = kp[0], vc = vp[0];

    for (int t = 0; t < Tt; t++) {
        const int p = t & 1;
        if (!half) rk[p][j] = make_float2(rc, kc);
        const float vj = vc;
        __syncthreads();

        if (t + 1 < Tt) {
            const size_t ofs = (size_t)(t + 1) * Cc;
            rc = rp[ofs]; kc = kp[ofs]; vc = vp[ofs];
        }

        float y = 0.f;
#pragma unroll
        for (int q = 0; q < 32; q++) {
            const float2 x = rk[p][i0 + q];
            const float kv = x.y * vj;
            y = fmaf(x.x, fmaf(u[q], kv, S[q]), y);
            S[q] = fmaf(w[q], S[q], kv);
        }
        part[p][half][j] = y;
        __syncthreads();

        if (!half) yp[(size_t)t * Cc] = part[p][0][j] + part[p][1][j];
    }
}

// ---------------------------------------------------------------------------
// GroupNorm(y/8)*ln_w+ln_b, multiply silu-gate, split bf16 hi/lo
// ---------------------------------------------------------------------------
__global__ __launch_bounds__(256)
void gnorm_k(const float* __restrict__ lnw, const float* __restrict__ lnb)
{
    const int gidx = blockIdx.x * 8 + (threadIdx.x >> 5);
    const int lane = threadIdx.x & 31;
    const int h = gidx & (Hh - 1);
    const size_t base = (size_t)gidx * HSs;

    float y0 = g_y[base + lane] * DIVI;
    float y1 = g_y[base + 32 + lane] * DIVI;

    float s = y0 + y1;
#pragma unroll
    for (int o = 16; o; o >>= 1) s += __shfl_xor_sync(0xFFFFFFFFu, s, o);
    const float mean = s * (1.f / 64.f);

    const float d0 = y0 - mean, d1 = y1 - mean;
    float v = d0 * d0 + d1 * d1;
#pragma unroll
    for (int o = 16; o; o >>= 1) v += __shfl_xor_sync(0xFFFFFFFFu, v, o);
    const float rstd = rsqrtf(v * (1.f / 64.f) + 1e-5f);

    const int li = h * HSs + lane;
    const float p0 = (d0 * rstd * lnw[li] + lnb[li]) * g_g[base + lane];
    const float p1 = (d1 * rstd * lnw[li + 32] + lnb[li + 32]) * g_g[base + 32 + lane];

    __nv_bfloat16 h0, l0, h1, l1;
    split1(p0, h0, l0); split1(p1, h1, l1);
    g_fah[base + lane] = h0;      g_fal[base + lane] = l0;
    g_fah[base + 32 + lane] = h1; g_fal[base + 32 + lane] = l1;
}

// ---------------------------------------------------------------------------
// launch
// ---------------------------------------------------------------------------
extern "C" void kernel_launch(void* const* d_in, const int* in_sizes, int n_in,
                              void* d_out, int out_size)
{
    const float* x     = (const float*)d_in[0];
    const float* tmk   = (const float*)d_in[1];
    const float* tmv   = (const float*)d_in[2];
    const float* tmr   = (const float*)d_in[3];
    const float* tmg   = (const float*)d_in[4];
    const float* decay = (const float*)d_in[5];
    const float* faaaa = (const float*)d_in[6];
    const float* Wr    = (const float*)d_in[7];
    const float* Wk    = (const float*)d_in[8];
    const float* Wv    = (const float*)d_in[9];
    const float* Wg    = (const float*)d_in[10];
    const float* Wo    = (const float*)d_in[11];
    const float* lnw   = (const float*)d_in[12];
    const float* lnb   = (const float*)d_in[13];
    float* out = (float*)d_out;

    cudaFuncSetAttribute(mm_hmma<0>, cudaFuncAttributeMaxDynamicSharedMemorySize, GEMM_SMEM);
    cudaFuncSetAttribute(mm_hmma<1>, cudaFuncAttributeMaxDynamicSharedMemorySize, GEMM_SMEM);

    void *pah, *pal, *pwh, *pwl, *pfah, *pfal, *pr, *pk, *pv, *pg;
    cudaGetSymbolAddress(&pah, g_ah);
    cudaGetSymbolAddress(&pal, g_al);
    cudaGetSymbolAddress(&pwh, g_wh);
    cudaGetSymbolAddress(&pwl, g_wl);
    cudaGetSymbolAddress(&pfah, g_fah);
    cudaGetSymbolAddress(&pfal, g_fal);
    cudaGetSymbolAddress(&pr, g_r);
    cudaGetSymbolAddress(&pk, g_k);
    cudaGetSymbolAddress(&pv, g_v);
    cudaGetSymbolAddress(&pg, g_g);
    const __nv_bfloat16* ah = (const __nv_bfloat16*)pah;
    const __nv_bfloat16* al = (const __nv_bfloat16*)pal;
    const __nv_bfloat16* wh = (const __nv_bfloat16*)pwh;
    const __nv_bfloat16* wl = (const __nv_bfloat16*)pwl;

    conv_x<<<(unsigned)(MK / 4 / 256), 256>>>(x, tmr, tmk, tmv, tmg);
    conv_w<<<dim3(Cc / 32, Cc / 32, 5), 256>>>(Wr, Wk, Wv, Wg, Wo);

    dim3 grid(Cc / 128, Mtot / 128);   // (16, 128)

    mm_hmma<0><<<grid, 256, GEMM_SMEM>>>(ah + 0 * MK, al + 0 * MK, wh + 0 * NK, wl + 0 * NK, (float*)pr);
    mm_hmma<0><<<grid, 256, GEMM_SMEM>>>(ah + 1 * MK, al + 1 * MK, wh + 1 * NK, wl + 1 * NK, (float*)pk);
    mm_hmma<0><<<grid, 256, GEMM_SMEM>>>(ah + 2 * MK, al + 2 * MK, wh + 2 * NK, wl + 2 * NK, (float*)pv);
    mm_hmma<1><<<grid, 256, GEMM_SMEM>>>(ah + 3 * MK, al + 3 * MK, wh + 3 * NK, wl + 3 * NK, (float*)pg);

    wkv5_k<<<Bb * Hh, 128>>>(decay, faaaa);

    gnorm_k<<<(Bb * Tt * Hh) / 8, 256>>>(lnw, lnb);

    mm_hmma<0><<<grid, 256, GEMM_SMEM>>>((const __nv_bfloat16*)pfah, (const __nv_bfloat16*)pfal,
                                         wh + 4 * NK, wl + 4 * NK, out);
}